// round 2
// baseline (speedup 1.0000x reference)
#include <cuda_runtime.h>
#include <cstdint>

// Problem constants (fixed by the dataset)
#define D      1024   // bond dimension
#define NSYM   32     // physical dimension / alphabet
#define F      1024   // chain length
#define NCTA   128    // persistent grid (must be <= 148 SMs: single wave, spin-safe)
#define TPB    256    // 8 warps per CTA -> 1024 warps == D outputs

// Transposed cores: g_MT[s][j][i] = core[s][i][j]  (so out[j] = dot(MT[s][j][:], v))
__device__ float g_MT[NSYM][D][D];

// Tagged ping-pong v buffers: each entry is {float value (lo 32), uint tag (hi 32)}
// written/read as a single aligned 8-byte transaction (atomic visibility).
__device__ unsigned long long g_vbuf[2][D];

__device__ __forceinline__ unsigned long long ld_cg_u64(const unsigned long long* p) {
    unsigned long long v;
    asm volatile("ld.global.cg.b64 %0, [%1];" : "=l"(v) : "l"(p) : "memory");
    return v;
}
__device__ __forceinline__ void st_cg_u64(unsigned long long* p, unsigned long long v) {
    asm volatile("st.global.cg.b64 [%0], %1;" :: "l"(p), "l"(v) : "memory");
}

// ---------------------------------------------------------------------------
// K1: transpose all 32 cores (coalesced via 32x32 smem tiles)
// grid (32 j-tiles, 32 i-tiles, 32 symbols), block (32, 8)
// ---------------------------------------------------------------------------
__global__ void transpose_kernel(const float* __restrict__ core) {
    __shared__ float tile[32][33];
    const int s  = blockIdx.z;
    const int i0 = blockIdx.y * 32;
    const int j0 = blockIdx.x * 32;
    const int tx = threadIdx.x, ty = threadIdx.y;

    const float* src = core + ((size_t)s * D + i0) * D + j0;
    #pragma unroll
    for (int r = 0; r < 32; r += 8)
        tile[ty + r][tx] = src[(size_t)(ty + r) * D + tx];   // tile[a][b] = core[i0+a][j0+b]
    __syncthreads();

    float* dst = &g_MT[s][j0][i0];
    #pragma unroll
    for (int r = 0; r < 32; r += 8)
        dst[(size_t)(ty + r) * D + tx] = tile[tx][ty + r];   // MT[j0+ty+r][i0+tx] = core[i0+tx][j0+ty+r]
}

// ---------------------------------------------------------------------------
// K2: initialize tagged v buffers. buf0 = {left_boundary, tag 0}; buf1 = invalid.
// ---------------------------------------------------------------------------
__global__ void init_kernel(const float* __restrict__ lb) {
    int j = blockIdx.x * blockDim.x + threadIdx.x;
    if (j < D) {
        g_vbuf[0][j] = (unsigned long long)__float_as_uint(lb[j]);        // tag 0 in hi bits
        g_vbuf[1][j] = 0xFFFFFFFF00000000ull;                             // invalid tag
    }
}

// ---------------------------------------------------------------------------
// K3: persistent chain kernel. warp w (global) owns output column j = w.
// Per step t: prefetch MT[x[t-1]][j][:] into regs -> poll tagged v_{t-1} ->
// stage v in smem -> dot -> warp-reduce -> publish {v_t[j], t} with one st.cg.b64.
// ---------------------------------------------------------------------------
__global__ void __launch_bounds__(TPB, 1) chain_kernel(const int* __restrict__ x) {
    __shared__ float sv[D];
    __shared__ int   sx[F];

    const int tid  = threadIdx.x;
    const int warp = tid >> 5;
    const int lane = tid & 31;
    const int j    = blockIdx.x * (TPB / 32) + warp;   // output column

    for (int k = tid; k < F; k += TPB) sx[k] = x[k];
    __syncthreads();

    for (int t = 1; t <= F; ++t) {
        // ---- prefetch matrix row for this step (independent of the poll) ----
        const int s = sx[t - 1];
        const float4* row = reinterpret_cast<const float4*>(&g_MT[s][j][0]);
        float4 m[8];
        #pragma unroll
        for (int k = 0; k < 8; ++k)
            m[k] = row[k * 32 + lane];                 // elements k*128 + lane*4 .. +3

        // ---- poll tagged v_{t-1} (4 entries per thread, 1024 total per CTA) ----
        const unsigned long long* src = g_vbuf[(t - 1) & 1];
        unsigned long long p[4];
        int ok;
        do {
            #pragma unroll
            for (int q = 0; q < 4; ++q)
                p[q] = ld_cg_u64(&src[tid * 4 + q]);
            ok = 1;
            #pragma unroll
            for (int q = 0; q < 4; ++q)
                ok &= ((unsigned)(p[q] >> 32) == (unsigned)(t - 1));
        } while (!__syncthreads_and(ok));

        #pragma unroll
        for (int q = 0; q < 4; ++q)
            sv[tid * 4 + q] = __uint_as_float((unsigned)p[q]);
        __syncthreads();

        // ---- dot(MT[s][j][:], v) from prefetched regs + smem v ----
        float acc = 0.f;
        #pragma unroll
        for (int k = 0; k < 8; ++k) {
            const float4 v = *reinterpret_cast<const float4*>(&sv[k * 128 + lane * 4]);
            acc += m[k].x * v.x + m[k].y * v.y + m[k].z * v.z + m[k].w * v.w;
        }
        #pragma unroll
        for (int off = 16; off; off >>= 1)
            acc += __shfl_xor_sync(0xFFFFFFFFu, acc, off);

        if (lane == 0) {
            unsigned long long outp =
                ((unsigned long long)(unsigned)t << 32) | (unsigned long long)__float_as_uint(acc);
            st_cg_u64(&g_vbuf[t & 1][j], outp);
        }
        // sv reuse is safe: next iteration's sv writes happen only after the next
        // __syncthreads_and barrier, which every thread reaches only after
        // finishing this iteration's dot.
    }
}

// ---------------------------------------------------------------------------
// K4: final reduction  out = dot(v_F, right_boundary).  F even -> v_F in buf 0.
// ---------------------------------------------------------------------------
__global__ void final_kernel(const float* __restrict__ rb, float* __restrict__ out) {
    __shared__ float red[32];
    const int tid = threadIdx.x;      // 1024 threads
    const unsigned long long p = g_vbuf[F & 1][tid];
    float acc = __uint_as_float((unsigned)p) * rb[tid];
    #pragma unroll
    for (int off = 16; off; off >>= 1)
        acc += __shfl_xor_sync(0xFFFFFFFFu, acc, off);
    if ((tid & 31) == 0) red[tid >> 5] = acc;
    __syncthreads();
    if (tid < 32) {
        float a = red[tid];
        #pragma unroll
        for (int off = 16; off; off >>= 1)
            a += __shfl_xor_sync(0xFFFFFFFFu, a, off);
        if (tid == 0) out[0] = a;
    }
}

// ---------------------------------------------------------------------------
// Inputs (metadata order): x [F] int32, core [d*D*D] f32, left_boundary [D] f32,
// right_boundary [D] f32. Output: 1 float.
// ---------------------------------------------------------------------------
extern "C" void kernel_launch(void* const* d_in, const int* in_sizes, int n_in,
                              void* d_out, int out_size) {
    const int*   x    = (const int*)  d_in[0];
    const float* core = (const float*)d_in[1];
    const float* lb   = (const float*)d_in[2];
    const float* rb   = (const float*)d_in[3];
    float*       out  = (float*)d_out;

    transpose_kernel<<<dim3(32, 32, 32), dim3(32, 8)>>>(core);
    init_kernel<<<1, D>>>(lb);
    chain_kernel<<<NCTA, TPB>>>(x);
    final_kernel<<<1, D>>>(rb, out);
}